// round 14
// baseline (speedup 1.0000x reference)
#include <cuda_runtime.h>
#include <cuda_fp16.h>
#include <mma.h>
#include <math.h>

using namespace nvcuda;

// ---------------- problem constants ----------------
#define NN 10000
#define EE 320000
#define HH 128
#define GG 50
#define LL 6
#define KTAB 2048
#define PTS 16

#define AP 136                   // padded smem row stride (halves)
#define ASZ2 (64 * AP * 2)       // 17408
#define BSZ2 (128 * AP * 2)      // 34816
#define SCW  576                 // per-warp scratch floats (16 x 36)
#define SCSZ (8 * SCW * 4)       // 18432
#define SMEM_CHAIN2 (ASZ2 + 2 * BSZ2 + SCSZ)  // 105472

#define DMAXT 8.6605f
#define TABSCALE ((float)(KTAB - 1) / DMAXT)
#define DSTEP (DMAXT / (float)(KTAB - 1))
#define GSTEP (10.0f / 49.0f)
#define GCOEFF (-0.5f / (GSTEP * GSTEP))
#define LN2F 0.6931471805599453f
#define PIF 3.14159265358979323846f

// ---------------- scratch ----------------
__device__ __half g_tab[LL * KTAB * HH];
__device__ __half g_xh[NN * HH];
__device__ __half g_aggh[NN * HH];
__device__ __half g_hh[NN * HH];       // fp16 copy of current h
__device__ __half g_ph[NN * HH];       // q = h_l @ W1[l+1]
__device__ __half g_w1t[LL * HH * HH];
__device__ __half g_w2t[LL * HH * HH];
__device__ __half g_w3t[LL * HH * HH];
__device__ __half g_w31t[(LL - 1) * HH * HH];  // W3[l] @ W1[l+1], [n][k]
__device__ float  g_c31[(LL - 1) * HH];        // b3[l] @ W1[l+1]
__device__ int    g_deg[NN];
__device__ int    g_start[NN + 1];
__device__ int    g_cursor[NN];
__device__ int2   g_me[EE];
__device__ int2   g_se[EE];

__device__ __forceinline__ float sspf(float v) {
    float sp = (v > 20.f) ? v : log1pf(expf(v));
    return sp - LN2F;
}

// ---------------- weight transpose + fp16 convert ----------------
__global__ void k_wconv(const float* __restrict__ w1,
                        const float* __restrict__ w2,
                        const float* __restrict__ w3)
{
    const int SET = LL * HH * HH;
    int idx = blockIdx.x * blockDim.x + threadIdx.x;
    if (idx >= 3 * SET) return;
    int which = idx / SET;
    int r = idx - which * SET;
    int l = r >> 14;
    int k = (r >> 7) & 127;
    int n = r & 127;
    const float* in = (which == 0) ? w1 : (which == 1) ? w2 : w3;
    __half* out = (which == 0) ? g_w1t : (which == 1) ? g_w2t : g_w3t;
    out[l * HH * HH + n * HH + k] = __float2half(in[r]);
}

// ---------------- fused-weight precompute ----------------
__global__ void k_w31(const float* __restrict__ lin_w,
                      const float* __restrict__ lin1_w,
                      const float* __restrict__ lin_b)
{
    const int TOT1 = (LL - 1) * HH * HH;
    int idx = blockIdx.x * blockDim.x + threadIdx.x;
    if (idx < TOT1) {
        int l = idx >> 14;
        int rem = idx & 16383;
        int k = (rem >> 7) & 127;
        int n = rem & 127;
        const float* A = lin_w + (size_t)l * HH * HH;         // [k][j]
        const float* B = lin1_w + (size_t)(l + 1) * HH * HH;  // [j][n]
        float s = 0.f;
        for (int j = 0; j < HH; j++)
            s += A[k * HH + j] * B[j * HH + n];
        g_w31t[(size_t)l * HH * HH + n * HH + k] = __float2half(s);
    } else if (idx < TOT1 + (LL - 1) * HH) {
        int r = idx - TOT1;
        int l = r >> 7, n = r & 127;
        const float* B = lin1_w + (size_t)(l + 1) * HH * HH;
        float s = 0.f;
        for (int k = 0; k < HH; k++)
            s += lin_b[l * HH + k] * B[k * HH + n];
        g_c31[r] = s;
    }
}

// ---------------- embedding ----------------
__global__ void k_embed(const int* __restrict__ z, const float* __restrict__ emb,
                        float* __restrict__ h, int N) {
    int idx = blockIdx.x * blockDim.x + threadIdx.x;
    if (idx >= N * 32) return;
    int n = idx >> 5, q = idx & 31;
    float4 v = ((const float4*)emb)[z[n] * 32 + q];
    ((float4*)h)[idx] = v;
    uint2 p;
    __half2 h0 = __floats2half2_rn(v.x, v.y);
    __half2 h1 = __floats2half2_rn(v.z, v.w);
    p.x = *(unsigned int*)&h0;
    p.y = *(unsigned int*)&h1;
    ((uint2*)g_hh)[idx] = p;
}

__global__ void k_zero(int n) {
    int i = blockIdx.x * blockDim.x + threadIdx.x;
    if (i < n) g_deg[i] = 0;
}

// ---------------- row-GEMM: out = g_hh @ W1t[wl] (to g_xh or g_ph) --------
template <bool TO_PH>
__global__ void __launch_bounds__(256) k_rowgemm(int wl, int N) {
    __shared__ __align__(16) char smem_raw[64 * AP * 2 + 128 * AP * 2];
    __half* As = (__half*)smem_raw;
    __half* Bs = (__half*)(smem_raw + 64 * AP * 2);
    float*  Os = (float*)smem_raw;

    const int tid = threadIdx.x;
    const int wid = tid >> 5;
    const int m0 = blockIdx.x * 64;
    const __half* Bw = g_w1t + (size_t)wl * HH * HH;

#pragma unroll
    for (int i = 0; i < 4; i++) {
        int lin = i * 256 + tid;
        int r = lin >> 4, c = lin & 15;
        int gr = m0 + r;
        uint4 v = make_uint4(0, 0, 0, 0);
        if (gr < N) v = *(const uint4*)(g_hh + (size_t)gr * HH + c * 8);
        *(uint4*)(As + r * AP + c * 8) = v;
    }
#pragma unroll
    for (int i = 0; i < 8; i++) {
        int lin = i * 256 + tid;
        int r = lin >> 4, c = lin & 15;
        *(uint4*)(Bs + r * AP + c * 8) = *(const uint4*)(Bw + lin * 8);
    }
    __syncthreads();

    const int wm = wid & 3;
    const int wn = wid >> 2;
    wmma::fragment<wmma::accumulator, 16, 16, 16, float> accf[4];
#pragma unroll
    for (int n = 0; n < 4; n++) wmma::fill_fragment(accf[n], 0.f);
#pragma unroll
    for (int ks = 0; ks < 8; ks++) {
        wmma::fragment<wmma::matrix_a, 16, 16, 16, __half, wmma::row_major> af;
        wmma::load_matrix_sync(af, As + (wm * 16) * AP + ks * 16, AP);
#pragma unroll
        for (int n = 0; n < 4; n++) {
            wmma::fragment<wmma::matrix_b, 16, 16, 16, __half, wmma::col_major> bf;
            wmma::load_matrix_sync(bf, Bs + (wn * 64 + n * 16) * AP + ks * 16, AP);
            wmma::mma_sync(accf[n], af, bf, accf[n]);
        }
    }
    __syncthreads();
#pragma unroll
    for (int n = 0; n < 4; n++)
        wmma::store_matrix_sync(Os + (wm * 16) * 132 + wn * 64 + n * 16,
                                accf[n], 132, wmma::mem_row_major);
    __syncthreads();

    __half* outb = TO_PH ? g_ph : g_xh;
#pragma unroll
    for (int i = 0; i < 8; i++) {
        int lin = i * 256 + tid;
        int r = lin >> 5, c4 = lin & 31;
        int gr = m0 + r;
        if (gr >= N) continue;
        float4 v = *(float4*)(Os + r * 132 + c4 * 4);
        uint2 p;
        __half2 h0 = __floats2half2_rn(v.x, v.y);
        __half2 h1 = __floats2half2_rn(v.z, v.w);
        p.x = *(unsigned int*)&h0;
        p.y = *(unsigned int*)&h1;
        *(uint2*)(outb + (size_t)gr * HH + c4 * 4) = p;
    }
}

// ---------------- Wf(d) table build ----------------
__global__ void __launch_bounds__(128) k_table(
    const float* __restrict__ w1, const float* __restrict__ b1,
    const float* __restrict__ w2, const float* __restrict__ b2)
{
    __shared__ float ea[PTS][GG];
    __shared__ float t1[PTS][HH];
    const int l  = blockIdx.y;
    const int k0 = blockIdx.x * PTS;
    const int f  = threadIdx.x;

    for (int idx = f; idx < PTS * GG; idx += 128) {
        int p = idx / GG, g = idx % GG;
        float d  = (float)(k0 + p) * DSTEP;
        float dd = d - (float)g * GSTEP;
        ea[p][g] = expf(GCOEFF * dd * dd);
    }
    __syncthreads();

    float acc[PTS];
#pragma unroll
    for (int p = 0; p < PTS; p++) acc[p] = 0.f;
    const float* W1 = w1 + l * GG * HH;
    for (int g = 0; g < GG; g++) {
        float w = W1[g * HH + f];
#pragma unroll
        for (int p = 0; p < PTS; p++) acc[p] += ea[p][g] * w;
    }
    float bb = b1[l * HH + f];
#pragma unroll
    for (int p = 0; p < PTS; p++) t1[p][f] = sspf(acc[p] + bb);
    __syncthreads();

#pragma unroll
    for (int p = 0; p < PTS; p++) acc[p] = 0.f;
    const float* W2 = w2 + l * HH * HH;
    for (int ff = 0; ff < HH; ff++) {
        float w = W2[ff * HH + f];
#pragma unroll
        for (int p = 0; p < PTS; p++) acc[p] += t1[p][ff] * w;
    }
    float b2v = b2[l * HH + f];
#pragma unroll
    for (int p = 0; p < PTS; p++) {
        float d = (float)(k0 + p) * DSTEP;
        float C = 0.5f * (cosf(d * (PIF / 10.f)) + 1.f);
        g_tab[(size_t)(l * KTAB + k0 + p) * HH + f] =
            __float2half((acc[p] + b2v) * C);
    }
}

// ---------------- CSR build ----------------
__global__ void k_prep(const int* __restrict__ ei, const float* __restrict__ pos, int E) {
    int stride = gridDim.x * blockDim.x;
    for (int e = blockIdx.x * blockDim.x + threadIdx.x; e < E; e += stride) {
        int r = ei[e], c = ei[E + e];
        float dx = pos[r * 3 + 0] - pos[c * 3 + 0];
        float dy = pos[r * 3 + 1] - pos[c * 3 + 1];
        float dz = pos[r * 3 + 2] - pos[c * 3 + 2];
        float d = sqrtf(dx * dx + dy * dy + dz * dz);
        float u = d * TABSCALE;
        int k = (int)u;
        if (k > KTAB - 2) k = KTAB - 2;
        if (k < 0) k = 0;
        float t = u - (float)k;
        g_me[e] = make_int2(r | (k << 14), __float_as_int(t));
        atomicAdd(&g_deg[c], 1);
    }
}

__global__ void __launch_bounds__(1024) k_scan(int n) {
    __shared__ int sw[32];
    const int PER = 10;
    int t = threadIdx.x, lane = t & 31, w = t >> 5;
    int base = t * PER;
    int local[PER];
    int sum = 0;
#pragma unroll
    for (int i = 0; i < PER; i++) {
        int v = (base + i < n) ? g_deg[base + i] : 0;
        local[i] = sum;
        sum += v;
    }
    int inc = sum;
#pragma unroll
    for (int off = 1; off < 32; off <<= 1) {
        int v = __shfl_up_sync(0xffffffffu, inc, off);
        if (lane >= off) inc += v;
    }
    if (lane == 31) sw[w] = inc;
    __syncthreads();
    if (w == 0) {
        int v = sw[lane];
        int s2 = v;
#pragma unroll
        for (int off = 1; off < 32; off <<= 1) {
            int u2 = __shfl_up_sync(0xffffffffu, s2, off);
            if (lane >= off) s2 += u2;
        }
        sw[lane] = s2 - v;
        if (lane == 31) g_start[n] = s2;
    }
    __syncthreads();
    int excl = sw[w] + inc - sum;
#pragma unroll
    for (int i = 0; i < PER; i++) {
        if (base + i < n) {
            int st = excl + local[i];
            g_start[base + i]  = st;
            g_cursor[base + i] = st;
        }
    }
}

__global__ void k_scatter(const int* __restrict__ ei, int E) {
    int stride = gridDim.x * blockDim.x;
    for (int e = blockIdx.x * blockDim.x + threadIdx.x; e < E; e += stride) {
        int c = ei[E + e];
        int p = atomicAdd(&g_cursor[c], 1);
        g_se[p] = g_me[e];
    }
}

// ---------------- message aggregation (unchanged from R11) ----------------
__global__ void __launch_bounds__(256) k_agg(int l, int N) {
    int warp = (blockIdx.x * 256 + threadIdx.x) >> 5;
    int lane = threadIdx.x & 31;
    if (warp >= N) return;
    const __half* __restrict__ tab = g_tab + (size_t)l * KTAB * HH;
    int beg = g_start[warp], end = g_start[warp + 1];
    const int flane = lane & 15;
    const int esub  = lane >> 4;
    float acc[8];
#pragma unroll
    for (int q = 0; q < 8; q++) acc[q] = 0.f;

    for (int e0 = beg; e0 < end; e0 += 32) {
        int idx = e0 + lane;
        int2 mv = make_int2(0, 0);
        if (idx < end) mv = __ldcs(&g_se[idx]);
        int cnt = min(32, end - e0);
        for (int s = 0; s < cnt; s += 4) {
            int j1 = s + esub;
            int j2 = s + 2 + esub;
            int mj1 = __shfl_sync(0xffffffffu, mv.x, j1 & 31);
            int ti1 = __shfl_sync(0xffffffffu, mv.y, j1 & 31);
            int mj2 = __shfl_sync(0xffffffffu, mv.x, j2 & 31);
            int ti2 = __shfl_sync(0xffffffffu, mv.y, j2 & 31);
            bool p1 = j1 < cnt, p2 = j2 < cnt;
            uint4 xr1, w01, w11, xr2, w02, w12;
            int k1 = mj1 >> 14, k2 = mj2 >> 14;
            int s1 = mj1 & 0x3FFF, s2v = mj2 & 0x3FFF;
            if (p1) {
                xr1 = __ldcs((const uint4*)(g_xh + (size_t)s1 * HH + flane * 8));
                w01 = *(const uint4*)(tab + (size_t)k1 * HH + flane * 8);
                w11 = *(const uint4*)(tab + (size_t)(k1 + 1) * HH + flane * 8);
            }
            if (p2) {
                xr2 = __ldcs((const uint4*)(g_xh + (size_t)s2v * HH + flane * 8));
                w02 = *(const uint4*)(tab + (size_t)k2 * HH + flane * 8);
                w12 = *(const uint4*)(tab + (size_t)(k2 + 1) * HH + flane * 8);
            }
            if (p1) {
                __half2 t2 = __float2half2_rn(__int_as_float(ti1));
                const __half2* xv = (const __half2*)&xr1;
                const __half2* a0 = (const __half2*)&w01;
                const __half2* a1 = (const __half2*)&w11;
#pragma unroll
                for (int q = 0; q < 4; q++) {
                    __half2 dd = __hsub2(a1[q], a0[q]);
                    __half2 w  = __hfma2(t2, dd, a0[q]);
                    __half2 p  = __hmul2(w, xv[q]);
                    float2 pf = __half22float2(p);
                    acc[q * 2 + 0] += pf.x;
                    acc[q * 2 + 1] += pf.y;
                }
            }
            if (p2) {
                __half2 t2 = __float2half2_rn(__int_as_float(ti2));
                const __half2* xv = (const __half2*)&xr2;
                const __half2* a0 = (const __half2*)&w02;
                const __half2* a1 = (const __half2*)&w12;
#pragma unroll
                for (int q = 0; q < 4; q++) {
                    __half2 dd = __hsub2(a1[q], a0[q]);
                    __half2 w  = __hfma2(t2, dd, a0[q]);
                    __half2 p  = __hmul2(w, xv[q]);
                    float2 pf = __half22float2(p);
                    acc[q * 2 + 0] += pf.x;
                    acc[q * 2 + 1] += pf.y;
                }
            }
        }
    }
#pragma unroll
    for (int q = 0; q < 8; q++)
        acc[q] += __shfl_xor_sync(0xffffffffu, acc[q], 16);

    if (esub == 0) {
        uint4 outv;
        __half2* op = (__half2*)&outv;
#pragma unroll
        for (int q = 0; q < 4; q++)
            op[q] = __floats2half2_rn(acc[q * 2], acc[q * 2 + 1]);
        *(uint4*)(g_aggh + (size_t)warp * HH + flane * 8) = outv;
    }
}

// ---------------- fused GEMM chain, 2 dependent stages ---------------------
// s1: u = ssp(agg @ W2 + b2) -> As (fp16)
// s2 (NEXT):  warps 0-3: h += u@W3 + b3 (and g_hh fp16)
//             warps 4-7: g_xh = u@W31 + c31 + q(g_ph)
// s2 (!NEXT): all warps:  h += u@W3 + b3
template <bool NEXT>
__global__ void __launch_bounds__(256, 2) k_chain(
    int l, const float* __restrict__ b2p, const float* __restrict__ b3p,
    float* __restrict__ h, int N)
{
    extern __shared__ __align__(16) char sm[];
    __half* As = (__half*)sm;
    __half* B0 = (__half*)(sm + ASZ2);
    __half* B1 = (__half*)(sm + ASZ2 + BSZ2);
    float*  SC = (float*)(sm + ASZ2 + 2 * BSZ2);

    const int tid  = threadIdx.x;
    const int wid  = tid >> 5;
    const int lane = tid & 31;
    const int m0   = blockIdx.x * 64;
    float* sc = SC + wid * SCW;

    typedef wmma::fragment<wmma::accumulator, 16, 16, 16, float> FragC;
    typedef wmma::fragment<wmma::matrix_a, 16, 16, 16, __half, wmma::row_major> FragA;
    typedef wmma::fragment<wmma::matrix_b, 16, 16, 16, __half, wmma::col_major> FragB;

    // load As <- g_aggh; B0 <- W2t[l]
#pragma unroll
    for (int i = 0; i < 4; i++) {
        int lin = i * 256 + tid;
        int r = lin >> 4, c = lin & 15;
        int gr = m0 + r;
        uint4 v = make_uint4(0, 0, 0, 0);
        if (gr < N) v = *(const uint4*)(g_aggh + (size_t)gr * HH + c * 8);
        *(uint4*)(As + r * AP + c * 8) = v;
    }
    {
        const __half* W2 = g_w2t + (size_t)l * HH * HH;
#pragma unroll
        for (int i = 0; i < 8; i++) {
            int lin = i * 256 + tid;
            int r = lin >> 4, c = lin & 15;
            *(uint4*)(B0 + r * AP + c * 8) = *(const uint4*)(W2 + lin * 8);
        }
    }
    __syncthreads();

    auto mma_tile = [&](const __half* Bs, int wm, int wn, FragC& c0, FragC& c1) {
        wmma::fill_fragment(c0, 0.f);
        wmma::fill_fragment(c1, 0.f);
#pragma unroll
        for (int ks = 0; ks < 8; ks++) {
            FragA af;
            wmma::load_matrix_sync(af, As + (wm * 16) * AP + ks * 16, AP);
            FragB b0, b1;
            wmma::load_matrix_sync(b0, Bs + (wn * 32) * AP + ks * 16, AP);
            wmma::load_matrix_sync(b1, Bs + (wn * 32 + 16) * AP + ks * 16, AP);
            wmma::mma_sync(c0, af, b0, c0);
            wmma::mma_sync(c1, af, b1, c1);
        }
    };

    // s1 MMA: each warp two 16x32 tiles: (wm1, wn0) and (wm1, wn0+2)
    const int wm1 = wid & 3;
    const int wn0 = wid >> 2;
    FragC s1c[4];
    mma_tile(B0, wm1, wn0,     s1c[0], s1c[1]);
    mma_tile(B0, wm1, wn0 + 2, s1c[2], s1c[3]);
    __syncthreads();  // all As/B0 reads complete

    // prefetch W3 -> B0 (+ W31 -> B1) while s1 epilogue computes
    {
        const __half* W3 = g_w3t + (size_t)l * HH * HH;
#pragma unroll
        for (int i = 0; i < 8; i++) {
            int lin = i * 256 + tid;
            int r = lin >> 4, c = lin & 15;
            *(uint4*)(B0 + r * AP + c * 8) = *(const uint4*)(W3 + lin * 8);
        }
        if (NEXT) {
            const __half* W31 = g_w31t + (size_t)l * HH * HH;
#pragma unroll
            for (int i = 0; i < 8; i++) {
                int lin = i * 256 + tid;
                int r = lin >> 4, c = lin & 15;
                *(uint4*)(B1 + r * AP + c * 8) = *(const uint4*)(W31 + lin * 8);
            }
        }
    }

    auto s1_epi = [&](FragC& c0, FragC& c1, int wm, int wn) {
        wmma::store_matrix_sync(sc, c0, 36, wmma::mem_row_major);
        wmma::store_matrix_sync(sc + 16, c1, 36, wmma::mem_row_major);
        __syncwarp();
#pragma unroll
        for (int i = 0; i < 8; i++) {
            int r = i * 2 + (lane >> 4);
            int c2 = (lane & 15) * 2;
            float v0 = sc[r * 36 + c2];
            float v1 = sc[r * 36 + c2 + 1];
            int col = wn * 32 + c2;
            v0 = sspf(v0 + b2p[col]);
            v1 = sspf(v1 + b2p[col + 1]);
            *(__half2*)(As + (size_t)(wm * 16 + r) * AP + col) =
                __floats2half2_rn(v0, v1);
        }
        __syncwarp();
    };
    s1_epi(s1c[0], s1c[1], wm1, wn0);
    s1_epi(s1c[2], s1c[3], wm1, wn0 + 2);
    __syncthreads();  // As(u) ready; B0/B1 loaded

    auto s2a_epi = [&](FragC& c0, FragC& c1, int wm, int wn, bool storeh) {
        wmma::store_matrix_sync(sc, c0, 36, wmma::mem_row_major);
        wmma::store_matrix_sync(sc + 16, c1, 36, wmma::mem_row_major);
        __syncwarp();
#pragma unroll
        for (int i = 0; i < 8; i++) {
            int r = i * 2 + (lane >> 4);
            int c2 = (lane & 15) * 2;
            float v0 = sc[r * 36 + c2];
            float v1 = sc[r * 36 + c2 + 1];
            int col = wn * 32 + c2;
            v0 += b3p[col];
            v1 += b3p[col + 1];
            int gr = m0 + wm * 16 + r;
            if (gr < N) {
                float2* hp = (float2*)(h + (size_t)gr * HH + col);
                float2 o = *hp;
                v0 += o.x; v1 += o.y;
                *hp = make_float2(v0, v1);
                if (storeh)
                    *(__half2*)(g_hh + (size_t)gr * HH + col) =
                        __floats2half2_rn(v0, v1);
            }
        }
        __syncwarp();
    };

    if (!NEXT) {
        FragC c0, c1;
        mma_tile(B0, wm1, wn0, c0, c1);
        s2a_epi(c0, c1, wm1, wn0, false);
        mma_tile(B0, wm1, wn0 + 2, c0, c1);
        s2a_epi(c0, c1, wm1, wn0 + 2, false);
    } else if (wid < 4) {
        // s2a: h update, 4 tiles (wm = wid)
#pragma unroll
        for (int wn = 0; wn < 4; wn++) {
            FragC c0, c1;
            mma_tile(B0, wid, wn, c0, c1);
            s2a_epi(c0, c1, wid, wn, true);
        }
    } else {
        // s2b: x_next = u@W31 + c31 + q -> g_xh, 4 tiles (wm = wid-4)
        int wm = wid - 4;
#pragma unroll
        for (int wn = 0; wn < 4; wn++) {
            FragC c0, c1;
            mma_tile(B1, wm, wn, c0, c1);
            wmma::store_matrix_sync(sc, c0, 36, wmma::mem_row_major);
            wmma::store_matrix_sync(sc + 16, c1, 36, wmma::mem_row_major);
            __syncwarp();
#pragma unroll
            for (int i = 0; i < 8; i++) {
                int r = i * 2 + (lane >> 4);
                int c2 = (lane & 15) * 2;
                float v0 = sc[r * 36 + c2];
                float v1 = sc[r * 36 + c2 + 1];
                int col = wn * 32 + c2;
                v0 += g_c31[l * HH + col];
                v1 += g_c31[l * HH + col + 1];
                int gr = m0 + wm * 16 + r;
                if (gr < N) {
                    __half2 qh = *(__half2*)(g_ph + (size_t)gr * HH + col);
                    float2 qf = __half22float2(qh);
                    v0 += qf.x; v1 += qf.y;
                    *(__half2*)(g_xh + (size_t)gr * HH + col) =
                        __floats2half2_rn(v0, v1);
                }
            }
            __syncwarp();
        }
    }
}

// ---------------- launch ----------------
extern "C" void kernel_launch(void* const* d_in, const int* in_sizes, int n_in,
                              void* d_out, int out_size)
{
    const int*   z      = (const int*)d_in[0];
    const float* pos    = (const float*)d_in[1];
    const int*   ei     = (const int*)d_in[2];
    const float* emb    = (const float*)d_in[3];
    const float* mlp_w1 = (const float*)d_in[4];
    const float* mlp_b1 = (const float*)d_in[5];
    const float* mlp_w2 = (const float*)d_in[6];
    const float* mlp_b2 = (const float*)d_in[7];
    const float* lin1_w = (const float*)d_in[8];
    const float* lin2_w = (const float*)d_in[9];
    const float* lin2_b = (const float*)d_in[10];
    const float* lin_w  = (const float*)d_in[11];
    const float* lin_b  = (const float*)d_in[12];

    const int N = in_sizes[0];
    const int E = in_sizes[2] / 2;
    float* h = (float*)d_out;

    static bool s_init = false;
    static cudaStream_t s_csr, s_tab, s_q;
    static cudaEvent_t s_evRoot, s_evCsr, s_evTab, s_evEmb;
    static cudaEvent_t s_evQ[LL], s_evC[LL];
    if (!s_init) {
        cudaFuncSetAttribute(k_chain<true>,
                             cudaFuncAttributeMaxDynamicSharedMemorySize, SMEM_CHAIN2);
        cudaFuncSetAttribute(k_chain<false>,
                             cudaFuncAttributeMaxDynamicSharedMemorySize, SMEM_CHAIN2);
        cudaStreamCreateWithFlags(&s_csr, cudaStreamNonBlocking);
        cudaStreamCreateWithFlags(&s_tab, cudaStreamNonBlocking);
        cudaStreamCreateWithFlags(&s_q, cudaStreamNonBlocking);
        cudaEventCreateWithFlags(&s_evRoot, cudaEventDisableTiming);
        cudaEventCreateWithFlags(&s_evCsr, cudaEventDisableTiming);
        cudaEventCreateWithFlags(&s_evTab, cudaEventDisableTiming);
        cudaEventCreateWithFlags(&s_evEmb, cudaEventDisableTiming);
        for (int i = 0; i < LL; i++) {
            cudaEventCreateWithFlags(&s_evQ[i], cudaEventDisableTiming);
            cudaEventCreateWithFlags(&s_evC[i], cudaEventDisableTiming);
        }
        s_init = true;
    }

    const int gb = (N + 63) / 64;
    const int ga = (N + 7) / 8;

    cudaEventRecord(s_evRoot, 0);
    cudaStreamWaitEvent(s_csr, s_evRoot, 0);
    cudaStreamWaitEvent(s_tab, s_evRoot, 0);

    // CSR stream
    k_zero<<<(N + 255) / 256, 256, 0, s_csr>>>(N);
    k_prep<<<313, 256, 0, s_csr>>>(ei, pos, E);
    k_scan<<<1, 1024, 0, s_csr>>>(N);
    k_scatter<<<313, 256, 0, s_csr>>>(ei, E);
    cudaEventRecord(s_evCsr, s_csr);

    // table stream: Wf tables + fused weights
    dim3 tg(KTAB / PTS, LL);
    k_table<<<tg, 128, 0, s_tab>>>(mlp_w1, mlp_b1, mlp_w2, mlp_b2);
    k_w31<<<((LL - 1) * HH * HH + (LL - 1) * HH + 255) / 256, 256, 0, s_tab>>>(
        lin_w, lin1_w, lin_b);
    cudaEventRecord(s_evTab, s_tab);

    // main stream
    k_wconv<<<(3 * LL * HH * HH + 255) / 256, 256>>>(lin1_w, lin2_w, lin_w);
    k_embed<<<(N * 32 + 255) / 256, 256>>>(z, emb, h, N);
    cudaEventRecord(s_evEmb, 0);
    k_rowgemm<false><<<gb, 256>>>(0, N);   // x_0 = h_0 @ W1[0]

    // q stream: q_0 = h_0 @ W1[1]
    cudaStreamWaitEvent(s_q, s_evEmb, 0);
    k_rowgemm<true><<<gb, 256, 0, s_q>>>(1, N);
    cudaEventRecord(s_evQ[0], s_q);

    cudaStreamWaitEvent(0, s_evCsr, 0);
    cudaStreamWaitEvent(0, s_evTab, 0);

    for (int l = 0; l < LL; l++) {
        k_agg<<<ga, 256>>>(l, N);
        if (l < LL - 1) {
            cudaStreamWaitEvent(0, s_evQ[l], 0);
            k_chain<true><<<gb, 256, SMEM_CHAIN2>>>(
                l, lin2_b + (size_t)l * HH, lin_b + (size_t)l * HH, h, N);
            cudaEventRecord(s_evC[l], 0);
            if (l < LL - 2) {
                cudaStreamWaitEvent(s_q, s_evC[l], 0);
                k_rowgemm<true><<<gb, 256, 0, s_q>>>(l + 2, N);
                cudaEventRecord(s_evQ[l + 1], s_q);
            }
        } else {
            k_chain<false><<<gb, 256, SMEM_CHAIN2>>>(
                l, lin2_b + (size_t)l * HH, lin_b + (size_t)l * HH, h, N);
        }
    }
}

// round 15
// speedup vs baseline: 1.0789x; 1.0789x over previous
#include <cuda_runtime.h>
#include <cuda_fp16.h>
#include <mma.h>
#include <math.h>

using namespace nvcuda;

// ---------------- problem constants ----------------
#define NN 10000
#define EE 320000
#define HH 128       // hidden = filters = 128
#define GG 50        // gaussians
#define LL 6         // layers
#define KTAB 2048    // distance-table resolution
#define PTS 16       // grid points per table-build block
#define CAP 96       // bucket capacity per node (deg ~ Poisson(32), 12 sigma)

#define AP 136       // padded smem row stride (halves) -> conflict-free
#define OP 132       // padded smem row stride (floats)

#define DMAXT 8.6605f
#define TABSCALE ((float)(KTAB - 1) / DMAXT)
#define DSTEP (DMAXT / (float)(KTAB - 1))
#define GSTEP (10.0f / 49.0f)
#define GCOEFF (-0.5f / (GSTEP * GSTEP))
#define LN2F 0.6931471805599453f
#define PIF 3.14159265358979323846f

// ---------------- scratch ----------------
__device__ __half g_tab[LL * KTAB * HH];
__device__ __half g_xh[NN * HH];
__device__ __half g_aggh[NN * HH];
__device__ __half g_hh[NN * HH];
__device__ __half g_w1t[LL * HH * HH];
__device__ __half g_w2t[LL * HH * HH];
__device__ __half g_w3t[LL * HH * HH];
__device__ int    g_deg[NN];
__device__ int2   g_se[NN * CAP];      // bucketed edge records per target node

__device__ __forceinline__ float sspf(float v) {
    float sp = (v > 20.f) ? v : log1pf(expf(v));
    return sp - LN2F;
}

// ---------------- weight transpose + fp16 convert ----------------
__global__ void k_wconv(const float* __restrict__ w1,
                        const float* __restrict__ w2,
                        const float* __restrict__ w3)
{
    const int SET = LL * HH * HH;
    int idx = blockIdx.x * blockDim.x + threadIdx.x;
    if (idx >= 3 * SET) return;
    int which = idx / SET;
    int r = idx - which * SET;
    int l = r >> 14;
    int k = (r >> 7) & 127;
    int n = r & 127;
    const float* in = (which == 0) ? w1 : (which == 1) ? w2 : w3;
    __half* out = (which == 0) ? g_w1t : (which == 1) ? g_w2t : g_w3t;
    out[l * HH * HH + n * HH + k] = __float2half(in[r]);
}

// ---------------- embedding ----------------
__global__ void k_embed(const int* __restrict__ z, const float* __restrict__ emb,
                        float* __restrict__ h, int N) {
    int idx = blockIdx.x * blockDim.x + threadIdx.x;
    if (idx >= N * 32) return;
    int n = idx >> 5, q = idx & 31;
    float4 v = ((const float4*)emb)[z[n] * 32 + q];
    ((float4*)h)[idx] = v;
    uint2 p;
    __half2 h0 = __floats2half2_rn(v.x, v.y);
    __half2 h1 = __floats2half2_rn(v.z, v.w);
    p.x = *(unsigned int*)&h0;
    p.y = *(unsigned int*)&h1;
    ((uint2*)g_hh)[idx] = p;
}

__global__ void k_zero(int n) {
    int i = blockIdx.x * blockDim.x + threadIdx.x;
    if (i < n) g_deg[i] = 0;
}

// ---------------- initial lin1 (padded smem) ----------------
__global__ void __launch_bounds__(256) k_lin1(int N) {
    __shared__ __align__(16) char smem_raw[64 * AP * 2 + 128 * AP * 2];
    __half* As = (__half*)smem_raw;
    __half* Bs = (__half*)(smem_raw + 64 * AP * 2);
    float*  Os = (float*)smem_raw;

    const int tid = threadIdx.x;
    const int wid = tid >> 5;
    const int m0 = blockIdx.x * 64;
    const __half* Bw = g_w1t;  // layer 0

#pragma unroll
    for (int i = 0; i < 4; i++) {
        int lin = i * 256 + tid;
        int r = lin >> 4, c = lin & 15;
        int gr = m0 + r;
        uint4 v = make_uint4(0, 0, 0, 0);
        if (gr < N) v = *(const uint4*)(g_hh + (size_t)gr * HH + c * 8);
        *(uint4*)(As + r * AP + c * 8) = v;
    }
#pragma unroll
    for (int i = 0; i < 8; i++) {
        int lin = i * 256 + tid;
        int r = lin >> 4, c = lin & 15;
        *(uint4*)(Bs + r * AP + c * 8) = *(const uint4*)(Bw + lin * 8);
    }
    __syncthreads();

    const int wm = wid & 3;
    const int wn = wid >> 2;
    wmma::fragment<wmma::accumulator, 16, 16, 16, float> accf[4];
#pragma unroll
    for (int n = 0; n < 4; n++) wmma::fill_fragment(accf[n], 0.f);
#pragma unroll
    for (int ks = 0; ks < 8; ks++) {
        wmma::fragment<wmma::matrix_a, 16, 16, 16, __half, wmma::row_major> af;
        wmma::load_matrix_sync(af, As + (wm * 16) * AP + ks * 16, AP);
#pragma unroll
        for (int n = 0; n < 4; n++) {
            wmma::fragment<wmma::matrix_b, 16, 16, 16, __half, wmma::col_major> bf;
            wmma::load_matrix_sync(bf, Bs + (wn * 64 + n * 16) * AP + ks * 16, AP);
            wmma::mma_sync(accf[n], af, bf, accf[n]);
        }
    }
    __syncthreads();
#pragma unroll
    for (int n = 0; n < 4; n++)
        wmma::store_matrix_sync(Os + (wm * 16) * OP + wn * 64 + n * 16,
                                accf[n], OP, wmma::mem_row_major);
    __syncthreads();

#pragma unroll
    for (int i = 0; i < 8; i++) {
        int lin = i * 256 + tid;
        int r = lin >> 5, c4 = lin & 31;
        int gr = m0 + r;
        if (gr >= N) continue;
        float4 v = *(float4*)(Os + r * OP + c4 * 4);
        uint2 p;
        __half2 h0 = __floats2half2_rn(v.x, v.y);
        __half2 h1 = __floats2half2_rn(v.z, v.w);
        p.x = *(unsigned int*)&h0;
        p.y = *(unsigned int*)&h1;
        *(uint2*)(g_xh + (size_t)gr * HH + c4 * 4) = p;
    }
}

// ---------------- Wf(d) table build ----------------
__global__ void __launch_bounds__(128) k_table(
    const float* __restrict__ w1, const float* __restrict__ b1,
    const float* __restrict__ w2, const float* __restrict__ b2)
{
    __shared__ float ea[PTS][GG];
    __shared__ float t1[PTS][HH];
    const int l  = blockIdx.y;
    const int k0 = blockIdx.x * PTS;
    const int f  = threadIdx.x;

    for (int idx = f; idx < PTS * GG; idx += 128) {
        int p = idx / GG, g = idx % GG;
        float d  = (float)(k0 + p) * DSTEP;
        float dd = d - (float)g * GSTEP;
        ea[p][g] = expf(GCOEFF * dd * dd);
    }
    __syncthreads();

    float acc[PTS];
#pragma unroll
    for (int p = 0; p < PTS; p++) acc[p] = 0.f;
    const float* W1 = w1 + l * GG * HH;
    for (int g = 0; g < GG; g++) {
        float w = W1[g * HH + f];
#pragma unroll
        for (int p = 0; p < PTS; p++) acc[p] += ea[p][g] * w;
    }
    float bb = b1[l * HH + f];
#pragma unroll
    for (int p = 0; p < PTS; p++) t1[p][f] = sspf(acc[p] + bb);
    __syncthreads();

#pragma unroll
    for (int p = 0; p < PTS; p++) acc[p] = 0.f;
    const float* W2 = w2 + l * HH * HH;
    for (int ff = 0; ff < HH; ff++) {
        float w = W2[ff * HH + f];
#pragma unroll
        for (int p = 0; p < PTS; p++) acc[p] += t1[p][ff] * w;
    }
    float b2v = b2[l * HH + f];
#pragma unroll
    for (int p = 0; p < PTS; p++) {
        float d = (float)(k0 + p) * DSTEP;
        float C = 0.5f * (cosf(d * (PIF / 10.f)) + 1.f);
        g_tab[(size_t)(l * KTAB + k0 + p) * HH + f] =
            __float2half((acc[p] + b2v) * C);
    }
}

// ---------------- one-pass bucketed CSR build ----------------
__global__ void k_prep(const int* __restrict__ ei, const float* __restrict__ pos, int E) {
    int stride = gridDim.x * blockDim.x;
    for (int e = blockIdx.x * blockDim.x + threadIdx.x; e < E; e += stride) {
        int r = ei[e], c = ei[E + e];
        float dx = pos[r * 3 + 0] - pos[c * 3 + 0];
        float dy = pos[r * 3 + 1] - pos[c * 3 + 1];
        float dz = pos[r * 3 + 2] - pos[c * 3 + 2];
        float d = sqrtf(dx * dx + dy * dy + dz * dz);
        float u = d * TABSCALE;
        int k = (int)u;
        if (k > KTAB - 2) k = KTAB - 2;
        if (k < 0) k = 0;
        float t = u - (float)k;
        int slot = atomicAdd(&g_deg[c], 1);
        if (slot < CAP)
            g_se[(size_t)c * CAP + slot] =
                make_int2(r | (k << 14), __float_as_int(t));
    }
}

// ---------------- message aggregation (fp16 lerp, MLP x2) ----------------
__global__ void __launch_bounds__(256) k_agg(int l, int N) {
    int warp = (blockIdx.x * 256 + threadIdx.x) >> 5;
    int lane = threadIdx.x & 31;
    if (warp >= N) return;
    const __half* __restrict__ tab = g_tab + (size_t)l * KTAB * HH;
    int beg = warp * CAP;
    int end = beg + min(g_deg[warp], CAP);
    const int flane = lane & 15;
    const int esub  = lane >> 4;
    float acc[8];
#pragma unroll
    for (int q = 0; q < 8; q++) acc[q] = 0.f;

    for (int e0 = beg; e0 < end; e0 += 32) {
        int idx = e0 + lane;
        int2 mv = make_int2(0, 0);
        if (idx < end) mv = __ldcs(&g_se[idx]);
        int cnt = min(32, end - e0);
        for (int s = 0; s < cnt; s += 4) {
            int j1 = s + esub;
            int j2 = s + 2 + esub;
            int mj1 = __shfl_sync(0xffffffffu, mv.x, j1 & 31);
            int ti1 = __shfl_sync(0xffffffffu, mv.y, j1 & 31);
            int mj2 = __shfl_sync(0xffffffffu, mv.x, j2 & 31);
            int ti2 = __shfl_sync(0xffffffffu, mv.y, j2 & 31);
            bool p1 = j1 < cnt, p2 = j2 < cnt;
            uint4 xr1, w01, w11, xr2, w02, w12;
            int k1 = mj1 >> 14, k2 = mj2 >> 14;
            int s1 = mj1 & 0x3FFF, s2v = mj2 & 0x3FFF;
            if (p1) {
                xr1 = __ldcs((const uint4*)(g_xh + (size_t)s1 * HH + flane * 8));
                w01 = *(const uint4*)(tab + (size_t)k1 * HH + flane * 8);
                w11 = *(const uint4*)(tab + (size_t)(k1 + 1) * HH + flane * 8);
            }
            if (p2) {
                xr2 = __ldcs((const uint4*)(g_xh + (size_t)s2v * HH + flane * 8));
                w02 = *(const uint4*)(tab + (size_t)k2 * HH + flane * 8);
                w12 = *(const uint4*)(tab + (size_t)(k2 + 1) * HH + flane * 8);
            }
            if (p1) {
                __half2 t2 = __float2half2_rn(__int_as_float(ti1));
                const __half2* xv = (const __half2*)&xr1;
                const __half2* a0 = (const __half2*)&w01;
                const __half2* a1 = (const __half2*)&w11;
#pragma unroll
                for (int q = 0; q < 4; q++) {
                    __half2 dd = __hsub2(a1[q], a0[q]);
                    __half2 w  = __hfma2(t2, dd, a0[q]);
                    __half2 p  = __hmul2(w, xv[q]);
                    float2 pf = __half22float2(p);
                    acc[q * 2 + 0] += pf.x;
                    acc[q * 2 + 1] += pf.y;
                }
            }
            if (p2) {
                __half2 t2 = __float2half2_rn(__int_as_float(ti2));
                const __half2* xv = (const __half2*)&xr2;
                const __half2* a0 = (const __half2*)&w02;
                const __half2* a1 = (const __half2*)&w12;
#pragma unroll
                for (int q = 0; q < 4; q++) {
                    __half2 dd = __hsub2(a1[q], a0[q]);
                    __half2 w  = __hfma2(t2, dd, a0[q]);
                    __half2 p  = __hmul2(w, xv[q]);
                    float2 pf = __half22float2(p);
                    acc[q * 2 + 0] += pf.x;
                    acc[q * 2 + 1] += pf.y;
                }
            }
        }
    }
#pragma unroll
    for (int q = 0; q < 8; q++)
        acc[q] += __shfl_xor_sync(0xffffffffu, acc[q], 16);

    if (esub == 0) {
        uint4 outv;
        __half2* op = (__half2*)&outv;
#pragma unroll
        for (int q = 0; q < 4; q++)
            op[q] = __floats2half2_rn(acc[q * 2], acc[q * 2 + 1]);
        *(uint4*)(g_aggh + (size_t)warp * HH + flane * 8) = outv;
    }
}

// ---------------- fused GEMM chain (padded smem) ----------------
template <bool NEXT>
__global__ void __launch_bounds__(256, 2) k_chain(
    int l, const float* __restrict__ b2p, const float* __restrict__ b3p,
    float* __restrict__ h, int N)
{
    extern __shared__ __align__(16) char sm[];
    __half* As = (__half*)sm;                               // 64 x AP
    __half* Bs = (__half*)(sm + 64 * AP * 2);               // 128 x AP
    float*  Os = (float*)(sm + 64 * AP * 2 + 128 * AP * 2); // 64 x OP

    const int tid = threadIdx.x;
    const int wid = tid >> 5;
    const int m0  = blockIdx.x * 64;

#pragma unroll
    for (int i = 0; i < 4; i++) {
        int lin = i * 256 + tid;
        int r = lin >> 4, c = lin & 15;
        int gr = m0 + r;
        uint4 v = make_uint4(0, 0, 0, 0);
        if (gr < N) v = *(const uint4*)(g_aggh + (size_t)gr * HH + c * 8);
        *(uint4*)(As + r * AP + c * 8) = v;
    }

    auto run_gemm = [&](const __half* __restrict__ Bw) {
        __syncthreads();
#pragma unroll
        for (int i = 0; i < 8; i++) {
            int lin = i * 256 + tid;
            int r = lin >> 4, c = lin & 15;
            *(uint4*)(Bs + r * AP + c * 8) = *(const uint4*)(Bw + lin * 8);
        }
        __syncthreads();
        for (int t2 = wid; t2 < 16; t2 += 8) {
            int wm = t2 & 3, wn = t2 >> 2;
            wmma::fragment<wmma::accumulator, 16, 16, 16, float> c0, c1;
            wmma::fill_fragment(c0, 0.f);
            wmma::fill_fragment(c1, 0.f);
#pragma unroll
            for (int ks = 0; ks < 8; ks++) {
                wmma::fragment<wmma::matrix_a, 16, 16, 16, __half, wmma::row_major> af;
                wmma::load_matrix_sync(af, As + (wm * 16) * AP + ks * 16, AP);
                wmma::fragment<wmma::matrix_b, 16, 16, 16, __half, wmma::col_major> bf0, bf1;
                wmma::load_matrix_sync(bf0, Bs + (wn * 32) * AP + ks * 16, AP);
                wmma::load_matrix_sync(bf1, Bs + (wn * 32 + 16) * AP + ks * 16, AP);
                wmma::mma_sync(c0, af, bf0, c0);
                wmma::mma_sync(c1, af, bf1, c1);
            }
            wmma::store_matrix_sync(Os + (wm * 16) * OP + wn * 32, c0, OP,
                                    wmma::mem_row_major);
            wmma::store_matrix_sync(Os + (wm * 16) * OP + wn * 32 + 16, c1, OP,
                                    wmma::mem_row_major);
        }
        __syncthreads();
    };

    // Stage 1: u = ssp(agg @ W2 + b2) -> As
    run_gemm(g_w2t + (size_t)l * HH * HH);
#pragma unroll
    for (int i = 0; i < 8; i++) {
        int lin = i * 256 + tid;
        int r = lin >> 5, c4 = lin & 31;
        float4 v = *(float4*)(Os + r * OP + c4 * 4);
        const float4 bi = *(const float4*)(b2p + c4 * 4);
        v.x = sspf(v.x + bi.x); v.y = sspf(v.y + bi.y);
        v.z = sspf(v.z + bi.z); v.w = sspf(v.w + bi.w);
        uint2 p;
        __half2 h0 = __floats2half2_rn(v.x, v.y);
        __half2 h1 = __floats2half2_rn(v.z, v.w);
        p.x = *(unsigned int*)&h0;
        p.y = *(unsigned int*)&h1;
        *(uint2*)(As + (size_t)r * AP + c4 * 4) = p;
    }

    // Stage 2: v = u @ W3 + b3 + h ; h = v -> As
    run_gemm(g_w3t + (size_t)l * HH * HH);
#pragma unroll
    for (int i = 0; i < 8; i++) {
        int lin = i * 256 + tid;
        int r = lin >> 5, c4 = lin & 31;
        int gr = m0 + r;
        float4 v = *(float4*)(Os + r * OP + c4 * 4);
        const float4 bi = *(const float4*)(b3p + c4 * 4);
        v.x += bi.x; v.y += bi.y; v.z += bi.z; v.w += bi.w;
        if (gr < N) {
            float4 o = *(float4*)(h + (size_t)gr * HH + c4 * 4);
            v.x += o.x; v.y += o.y; v.z += o.z; v.w += o.w;
            *(float4*)(h + (size_t)gr * HH + c4 * 4) = v;
        }
        uint2 p;
        __half2 h0 = __floats2half2_rn(v.x, v.y);
        __half2 h1 = __floats2half2_rn(v.z, v.w);
        p.x = *(unsigned int*)&h0;
        p.y = *(unsigned int*)&h1;
        *(uint2*)(As + (size_t)r * AP + c4 * 4) = p;
    }

    // Stage 3: x_next = v @ W1[l+1] -> g_xh
    if (NEXT) {
        run_gemm(g_w1t + (size_t)(l + 1) * HH * HH);
#pragma unroll
        for (int i = 0; i < 8; i++) {
            int lin = i * 256 + tid;
            int r = lin >> 5, c4 = lin & 31;
            int gr = m0 + r;
            if (gr >= N) continue;
            float4 v = *(float4*)(Os + r * OP + c4 * 4);
            uint2 p;
            __half2 h0 = __floats2half2_rn(v.x, v.y);
            __half2 h1 = __floats2half2_rn(v.z, v.w);
            p.x = *(unsigned int*)&h0;
            p.y = *(unsigned int*)&h1;
            *(uint2*)(g_xh + (size_t)gr * HH + c4 * 4) = p;
        }
    }
}

// ---------------- launch ----------------
extern "C" void kernel_launch(void* const* d_in, const int* in_sizes, int n_in,
                              void* d_out, int out_size)
{
    const int*   z      = (const int*)d_in[0];
    const float* pos    = (const float*)d_in[1];
    const int*   ei     = (const int*)d_in[2];
    const float* emb    = (const float*)d_in[3];
    const float* mlp_w1 = (const float*)d_in[4];
    const float* mlp_b1 = (const float*)d_in[5];
    const float* mlp_w2 = (const float*)d_in[6];
    const float* mlp_b2 = (const float*)d_in[7];
    const float* lin1_w = (const float*)d_in[8];
    const float* lin2_w = (const float*)d_in[9];
    const float* lin2_b = (const float*)d_in[10];
    const float* lin_w  = (const float*)d_in[11];
    const float* lin_b  = (const float*)d_in[12];

    const int N = in_sizes[0];
    const int E = in_sizes[2] / 2;
    float* h = (float*)d_out;

    const int SMEM_CHAIN = 64 * AP * 2 + 128 * AP * 2 + 64 * OP * 4;
    static bool s_init = false;
    static cudaStream_t s_csr, s_tab;
    static cudaEvent_t s_evRoot, s_evCsr, s_evTab;
    if (!s_init) {
        cudaFuncSetAttribute(k_chain<true>,
                             cudaFuncAttributeMaxDynamicSharedMemorySize, SMEM_CHAIN);
        cudaFuncSetAttribute(k_chain<false>,
                             cudaFuncAttributeMaxDynamicSharedMemorySize, SMEM_CHAIN);
        cudaStreamCreateWithFlags(&s_csr, cudaStreamNonBlocking);
        cudaStreamCreateWithFlags(&s_tab, cudaStreamNonBlocking);
        cudaEventCreateWithFlags(&s_evRoot, cudaEventDisableTiming);
        cudaEventCreateWithFlags(&s_evCsr, cudaEventDisableTiming);
        cudaEventCreateWithFlags(&s_evTab, cudaEventDisableTiming);
        s_init = true;
    }

    const int gb = (N + 63) / 64;
    const int ga = (N + 7) / 8;

    cudaEventRecord(s_evRoot, 0);
    cudaStreamWaitEvent(s_csr, s_evRoot, 0);
    cudaStreamWaitEvent(s_tab, s_evRoot, 0);

    // CSR stream (one-pass bucketing)
    k_zero<<<(N + 255) / 256, 256, 0, s_csr>>>(N);
    k_prep<<<625, 256, 0, s_csr>>>(ei, pos, E);
    cudaEventRecord(s_evCsr, s_csr);

    // table stream
    dim3 tg(KTAB / PTS, LL);
    k_table<<<tg, 128, 0, s_tab>>>(mlp_w1, mlp_b1, mlp_w2, mlp_b2);
    cudaEventRecord(s_evTab, s_tab);

    // main stream
    k_wconv<<<(3 * LL * HH * HH + 255) / 256, 256>>>(lin1_w, lin2_w, lin_w);
    k_embed<<<(N * 32 + 255) / 256, 256>>>(z, emb, h, N);
    k_lin1<<<gb, 256>>>(N);

    cudaStreamWaitEvent(0, s_evCsr, 0);
    cudaStreamWaitEvent(0, s_evTab, 0);

    for (int l = 0; l < LL; l++) {
        k_agg<<<ga, 256>>>(l, N);
        if (l < LL - 1)
            k_chain<true><<<gb, 256, SMEM_CHAIN>>>(
                l, lin2_b + (size_t)l * HH, lin_b + (size_t)l * HH, h, N);
        else
            k_chain<false><<<gb, 256, SMEM_CHAIN>>>(
                l, lin2_b + (size_t)l * HH, lin_b + (size_t)l * HH, h, N);
    }
}

// round 16
// speedup vs baseline: 1.1205x; 1.0386x over previous
#include <cuda_runtime.h>
#include <cuda_fp16.h>
#include <mma.h>
#include <math.h>

using namespace nvcuda;

// ---------------- problem constants ----------------
#define NN 10000
#define EE 320000
#define HH 128       // hidden = filters = 128
#define GG 50        // gaussians
#define LL 6         // layers
#define KTAB 1024    // table resolution: 256KB/layer -> ~L1-resident
#define PTS 16       // grid points per table-build block

#define AP 136       // padded smem row stride (halves) -> conflict-free
#define OP 132       // padded smem row stride (floats)

#define DMAXT 8.6605f
#define TABSCALE ((float)(KTAB - 1) / DMAXT)
#define DSTEP (DMAXT / (float)(KTAB - 1))
#define GSTEP (10.0f / 49.0f)
#define GCOEFF (-0.5f / (GSTEP * GSTEP))
#define LN2F 0.6931471805599453f
#define PIF 3.14159265358979323846f

// ---------------- scratch ----------------
__device__ __half g_tab[LL * KTAB * HH];
__device__ __half g_xh[NN * HH];
__device__ __half g_aggh[NN * HH];
__device__ __half g_hh[NN * HH];
__device__ __half g_w1t[LL * HH * HH];
__device__ __half g_w2t[LL * HH * HH];
__device__ __half g_w3t[LL * HH * HH];
__device__ int    g_deg[NN];
__device__ int    g_start[NN + 1];
__device__ int    g_cursor[NN];
__device__ int2   g_me[EE];
__device__ int2   g_se[EE];

__device__ __forceinline__ float sspf(float v) {
    float sp = (v > 20.f) ? v : log1pf(expf(v));
    return sp - LN2F;
}

// ---------------- weight transpose + fp16 convert ----------------
__global__ void k_wconv(const float* __restrict__ w1,
                        const float* __restrict__ w2,
                        const float* __restrict__ w3)
{
    const int SET = LL * HH * HH;
    int idx = blockIdx.x * blockDim.x + threadIdx.x;
    if (idx >= 3 * SET) return;
    int which = idx / SET;
    int r = idx - which * SET;
    int l = r >> 14;
    int k = (r >> 7) & 127;
    int n = r & 127;
    const float* in = (which == 0) ? w1 : (which == 1) ? w2 : w3;
    __half* out = (which == 0) ? g_w1t : (which == 1) ? g_w2t : g_w3t;
    out[l * HH * HH + n * HH + k] = __float2half(in[r]);
}

// ---------------- embedding ----------------
__global__ void k_embed(const int* __restrict__ z, const float* __restrict__ emb,
                        float* __restrict__ h, int N) {
    int idx = blockIdx.x * blockDim.x + threadIdx.x;
    if (idx >= N * 32) return;
    int n = idx >> 5, q = idx & 31;
    float4 v = ((const float4*)emb)[z[n] * 32 + q];
    ((float4*)h)[idx] = v;
    uint2 p;
    __half2 h0 = __floats2half2_rn(v.x, v.y);
    __half2 h1 = __floats2half2_rn(v.z, v.w);
    p.x = *(unsigned int*)&h0;
    p.y = *(unsigned int*)&h1;
    ((uint2*)g_hh)[idx] = p;
}

__global__ void k_zero(int n) {
    int i = blockIdx.x * blockDim.x + threadIdx.x;
    if (i < n) g_deg[i] = 0;
}

// ---------------- initial lin1 (padded smem) ----------------
__global__ void __launch_bounds__(256) k_lin1(int N) {
    __shared__ __align__(16) char smem_raw[64 * AP * 2 + 128 * AP * 2];
    __half* As = (__half*)smem_raw;
    __half* Bs = (__half*)(smem_raw + 64 * AP * 2);
    float*  Os = (float*)smem_raw;

    const int tid = threadIdx.x;
    const int wid = tid >> 5;
    const int m0 = blockIdx.x * 64;
    const __half* Bw = g_w1t;  // layer 0

#pragma unroll
    for (int i = 0; i < 4; i++) {
        int lin = i * 256 + tid;
        int r = lin >> 4, c = lin & 15;
        int gr = m0 + r;
        uint4 v = make_uint4(0, 0, 0, 0);
        if (gr < N) v = *(const uint4*)(g_hh + (size_t)gr * HH + c * 8);
        *(uint4*)(As + r * AP + c * 8) = v;
    }
#pragma unroll
    for (int i = 0; i < 8; i++) {
        int lin = i * 256 + tid;
        int r = lin >> 4, c = lin & 15;
        *(uint4*)(Bs + r * AP + c * 8) = *(const uint4*)(Bw + lin * 8);
    }
    __syncthreads();

    const int wm = wid & 3;
    const int wn = wid >> 2;
    wmma::fragment<wmma::accumulator, 16, 16, 16, float> accf[4];
#pragma unroll
    for (int n = 0; n < 4; n++) wmma::fill_fragment(accf[n], 0.f);
#pragma unroll
    for (int ks = 0; ks < 8; ks++) {
        wmma::fragment<wmma::matrix_a, 16, 16, 16, __half, wmma::row_major> af;
        wmma::load_matrix_sync(af, As + (wm * 16) * AP + ks * 16, AP);
#pragma unroll
        for (int n = 0; n < 4; n++) {
            wmma::fragment<wmma::matrix_b, 16, 16, 16, __half, wmma::col_major> bf;
            wmma::load_matrix_sync(bf, Bs + (wn * 64 + n * 16) * AP + ks * 16, AP);
            wmma::mma_sync(accf[n], af, bf, accf[n]);
        }
    }
    __syncthreads();
#pragma unroll
    for (int n = 0; n < 4; n++)
        wmma::store_matrix_sync(Os + (wm * 16) * OP + wn * 64 + n * 16,
                                accf[n], OP, wmma::mem_row_major);
    __syncthreads();

#pragma unroll
    for (int i = 0; i < 8; i++) {
        int lin = i * 256 + tid;
        int r = lin >> 5, c4 = lin & 31;
        int gr = m0 + r;
        if (gr >= N) continue;
        float4 v = *(float4*)(Os + r * OP + c4 * 4);
        uint2 p;
        __half2 h0 = __floats2half2_rn(v.x, v.y);
        __half2 h1 = __floats2half2_rn(v.z, v.w);
        p.x = *(unsigned int*)&h0;
        p.y = *(unsigned int*)&h1;
        *(uint2*)(g_xh + (size_t)gr * HH + c4 * 4) = p;
    }
}

// ---------------- Wf(d) table build ----------------
__global__ void __launch_bounds__(128) k_table(
    const float* __restrict__ w1, const float* __restrict__ b1,
    const float* __restrict__ w2, const float* __restrict__ b2)
{
    __shared__ float ea[PTS][GG];
    __shared__ float t1[PTS][HH];
    const int l  = blockIdx.y;
    const int k0 = blockIdx.x * PTS;
    const int f  = threadIdx.x;

    for (int idx = f; idx < PTS * GG; idx += 128) {
        int p = idx / GG, g = idx % GG;
        float d  = (float)(k0 + p) * DSTEP;
        float dd = d - (float)g * GSTEP;
        ea[p][g] = expf(GCOEFF * dd * dd);
    }
    __syncthreads();

    float acc[PTS];
#pragma unroll
    for (int p = 0; p < PTS; p++) acc[p] = 0.f;
    const float* W1 = w1 + l * GG * HH;
    for (int g = 0; g < GG; g++) {
        float w = W1[g * HH + f];
#pragma unroll
        for (int p = 0; p < PTS; p++) acc[p] += ea[p][g] * w;
    }
    float bb = b1[l * HH + f];
#pragma unroll
    for (int p = 0; p < PTS; p++) t1[p][f] = sspf(acc[p] + bb);
    __syncthreads();

#pragma unroll
    for (int p = 0; p < PTS; p++) acc[p] = 0.f;
    const float* W2 = w2 + l * HH * HH;
    for (int ff = 0; ff < HH; ff++) {
        float w = W2[ff * HH + f];
#pragma unroll
        for (int p = 0; p < PTS; p++) acc[p] += t1[p][ff] * w;
    }
    float b2v = b2[l * HH + f];
#pragma unroll
    for (int p = 0; p < PTS; p++) {
        float d = (float)(k0 + p) * DSTEP;
        float C = 0.5f * (cosf(d * (PIF / 10.f)) + 1.f);
        g_tab[(size_t)(l * KTAB + k0 + p) * HH + f] =
            __float2half((acc[p] + b2v) * C);
    }
}

// ---------------- CSR build (2-pass, proven R11 path) ----------------
__global__ void k_prep(const int* __restrict__ ei, const float* __restrict__ pos, int E) {
    int stride = gridDim.x * blockDim.x;
    for (int e = blockIdx.x * blockDim.x + threadIdx.x; e < E; e += stride) {
        int r = ei[e], c = ei[E + e];
        float dx = pos[r * 3 + 0] - pos[c * 3 + 0];
        float dy = pos[r * 3 + 1] - pos[c * 3 + 1];
        float dz = pos[r * 3 + 2] - pos[c * 3 + 2];
        float d = sqrtf(dx * dx + dy * dy + dz * dz);
        float u = d * TABSCALE;
        int k = (int)u;
        if (k > KTAB - 2) k = KTAB - 2;
        if (k < 0) k = 0;
        float t = u - (float)k;
        g_me[e] = make_int2(r | (k << 14), __float_as_int(t));
        atomicAdd(&g_deg[c], 1);
    }
}

__global__ void __launch_bounds__(1024) k_scan(int n) {
    __shared__ int sw[32];
    const int PER = 10;
    int t = threadIdx.x, lane = t & 31, w = t >> 5;
    int base = t * PER;
    int local[PER];
    int sum = 0;
#pragma unroll
    for (int i = 0; i < PER; i++) {
        int v = (base + i < n) ? g_deg[base + i] : 0;
        local[i] = sum;
        sum += v;
    }
    int inc = sum;
#pragma unroll
    for (int off = 1; off < 32; off <<= 1) {
        int v = __shfl_up_sync(0xffffffffu, inc, off);
        if (lane >= off) inc += v;
    }
    if (lane == 31) sw[w] = inc;
    __syncthreads();
    if (w == 0) {
        int v = sw[lane];
        int s2 = v;
#pragma unroll
        for (int off = 1; off < 32; off <<= 1) {
            int u2 = __shfl_up_sync(0xffffffffu, s2, off);
            if (lane >= off) s2 += u2;
        }
        sw[lane] = s2 - v;
        if (lane == 31) g_start[n] = s2;
    }
    __syncthreads();
    int excl = sw[w] + inc - sum;
#pragma unroll
    for (int i = 0; i < PER; i++) {
        if (base + i < n) {
            int st = excl + local[i];
            g_start[base + i]  = st;
            g_cursor[base + i] = st;
        }
    }
}

__global__ void k_scatter(const int* __restrict__ ei, int E) {
    int stride = gridDim.x * blockDim.x;
    for (int e = blockIdx.x * blockDim.x + threadIdx.x; e < E; e += stride) {
        int c = ei[E + e];
        int p = atomicAdd(&g_cursor[c], 1);
        g_se[p] = g_me[e];
    }
}

// ---------------- message aggregation ----------------
// fp16 lerp, MLP x2; streaming loads for x and meta keep L1 for the table,
// which at 256KB/layer is ~L1-resident (agg uses no smem -> full carveout).
__global__ void __launch_bounds__(256) k_agg(int l, int N) {
    int warp = (blockIdx.x * 256 + threadIdx.x) >> 5;
    int lane = threadIdx.x & 31;
    if (warp >= N) return;
    const __half* __restrict__ tab = g_tab + (size_t)l * KTAB * HH;
    int beg = g_start[warp], end = g_start[warp + 1];
    const int flane = lane & 15;
    const int esub  = lane >> 4;
    float acc[8];
#pragma unroll
    for (int q = 0; q < 8; q++) acc[q] = 0.f;

    for (int e0 = beg; e0 < end; e0 += 32) {
        int idx = e0 + lane;
        int2 mv = make_int2(0, 0);
        if (idx < end) mv = __ldcs(&g_se[idx]);
        int cnt = min(32, end - e0);
        for (int s = 0; s < cnt; s += 4) {
            int j1 = s + esub;
            int j2 = s + 2 + esub;
            int mj1 = __shfl_sync(0xffffffffu, mv.x, j1 & 31);
            int ti1 = __shfl_sync(0xffffffffu, mv.y, j1 & 31);
            int mj2 = __shfl_sync(0xffffffffu, mv.x, j2 & 31);
            int ti2 = __shfl_sync(0xffffffffu, mv.y, j2 & 31);
            bool p1 = j1 < cnt, p2 = j2 < cnt;
            uint4 xr1, w01, w11, xr2, w02, w12;
            int k1 = mj1 >> 14, k2 = mj2 >> 14;
            int s1 = mj1 & 0x3FFF, s2v = mj2 & 0x3FFF;
            if (p1) {
                xr1 = __ldcs((const uint4*)(g_xh + (size_t)s1 * HH + flane * 8));
                w01 = *(const uint4*)(tab + (size_t)k1 * HH + flane * 8);
                w11 = *(const uint4*)(tab + (size_t)(k1 + 1) * HH + flane * 8);
            }
            if (p2) {
                xr2 = __ldcs((const uint4*)(g_xh + (size_t)s2v * HH + flane * 8));
                w02 = *(const uint4*)(tab + (size_t)k2 * HH + flane * 8);
                w12 = *(const uint4*)(tab + (size_t)(k2 + 1) * HH + flane * 8);
            }
            if (p1) {
                __half2 t2 = __float2half2_rn(__int_as_float(ti1));
                const __half2* xv = (const __half2*)&xr1;
                const __half2* a0 = (const __half2*)&w01;
                const __half2* a1 = (const __half2*)&w11;
#pragma unroll
                for (int q = 0; q < 4; q++) {
                    __half2 dd = __hsub2(a1[q], a0[q]);
                    __half2 w  = __hfma2(t2, dd, a0[q]);
                    __half2 p  = __hmul2(w, xv[q]);
                    float2 pf = __half22float2(p);
                    acc[q * 2 + 0] += pf.x;
                    acc[q * 2 + 1] += pf.y;
                }
            }
            if (p2) {
                __half2 t2 = __float2half2_rn(__int_as_float(ti2));
                const __half2* xv = (const __half2*)&xr2;
                const __half2* a0 = (const __half2*)&w02;
                const __half2* a1 = (const __half2*)&w12;
#pragma unroll
                for (int q = 0; q < 4; q++) {
                    __half2 dd = __hsub2(a1[q], a0[q]);
                    __half2 w  = __hfma2(t2, dd, a0[q]);
                    __half2 p  = __hmul2(w, xv[q]);
                    float2 pf = __half22float2(p);
                    acc[q * 2 + 0] += pf.x;
                    acc[q * 2 + 1] += pf.y;
                }
            }
        }
    }
#pragma unroll
    for (int q = 0; q < 8; q++)
        acc[q] += __shfl_xor_sync(0xffffffffu, acc[q], 16);

    if (esub == 0) {
        uint4 outv;
        __half2* op = (__half2*)&outv;
#pragma unroll
        for (int q = 0; q < 4; q++)
            op[q] = __floats2half2_rn(acc[q * 2], acc[q * 2 + 1]);
        *(uint4*)(g_aggh + (size_t)warp * HH + flane * 8) = outv;
    }
}

// ---------------- fused GEMM chain (padded smem) ----------------
template <bool NEXT>
__global__ void __launch_bounds__(256, 2) k_chain(
    int l, const float* __restrict__ b2p, const float* __restrict__ b3p,
    float* __restrict__ h, int N)
{
    extern __shared__ __align__(16) char sm[];
    __half* As = (__half*)sm;                               // 64 x AP
    __half* Bs = (__half*)(sm + 64 * AP * 2);               // 128 x AP
    float*  Os = (float*)(sm + 64 * AP * 2 + 128 * AP * 2); // 64 x OP

    const int tid = threadIdx.x;
    const int wid = tid >> 5;
    const int m0  = blockIdx.x * 64;

#pragma unroll
    for (int i = 0; i < 4; i++) {
        int lin = i * 256 + tid;
        int r = lin >> 4, c = lin & 15;
        int gr = m0 + r;
        uint4 v = make_uint4(0, 0, 0, 0);
        if (gr < N) v = *(const uint4*)(g_aggh + (size_t)gr * HH + c * 8);
        *(uint4*)(As + r * AP + c * 8) = v;
    }

    auto run_gemm = [&](const __half* __restrict__ Bw) {
        __syncthreads();
#pragma unroll
        for (int i = 0; i < 8; i++) {
            int lin = i * 256 + tid;
            int r = lin >> 4, c = lin & 15;
            *(uint4*)(Bs + r * AP + c * 8) = *(const uint4*)(Bw + lin * 8);
        }
        __syncthreads();
        for (int t2 = wid; t2 < 16; t2 += 8) {
            int wm = t2 & 3, wn = t2 >> 2;
            wmma::fragment<wmma::accumulator, 16, 16, 16, float> c0, c1;
            wmma::fill_fragment(c0, 0.f);
            wmma::fill_fragment(c1, 0.f);
#pragma unroll
            for (int ks = 0; ks < 8; ks++) {
                wmma::fragment<wmma::matrix_a, 16, 16, 16, __half, wmma::row_major> af;
                wmma::load_matrix_sync(af, As + (wm * 16) * AP + ks * 16, AP);
                wmma::fragment<wmma::matrix_b, 16, 16, 16, __half, wmma::col_major> bf0, bf1;
                wmma::load_matrix_sync(bf0, Bs + (wn * 32) * AP + ks * 16, AP);
                wmma::load_matrix_sync(bf1, Bs + (wn * 32 + 16) * AP + ks * 16, AP);
                wmma::mma_sync(c0, af, bf0, c0);
                wmma::mma_sync(c1, af, bf1, c1);
            }
            wmma::store_matrix_sync(Os + (wm * 16) * OP + wn * 32, c0, OP,
                                    wmma::mem_row_major);
            wmma::store_matrix_sync(Os + (wm * 16) * OP + wn * 32 + 16, c1, OP,
                                    wmma::mem_row_major);
        }
        __syncthreads();
    };

    // Stage 1: u = ssp(agg @ W2 + b2) -> As
    run_gemm(g_w2t + (size_t)l * HH * HH);
#pragma unroll
    for (int i = 0; i < 8; i++) {
        int lin = i * 256 + tid;
        int r = lin >> 5, c4 = lin & 31;
        float4 v = *(float4*)(Os + r * OP + c4 * 4);
        const float4 bi = *(const float4*)(b2p + c4 * 4);
        v.x = sspf(v.x + bi.x); v.y = sspf(v.y + bi.y);
        v.z = sspf(v.z + bi.z); v.w = sspf(v.w + bi.w);
        uint2 p;
        __half2 h0 = __floats2half2_rn(v.x, v.y);
        __half2 h1 = __floats2half2_rn(v.z, v.w);
        p.x = *(unsigned int*)&h0;
        p.y = *(unsigned int*)&h1;
        *(uint2*)(As + (size_t)r * AP + c4 * 4) = p;
    }

    // Stage 2: v = u @ W3 + b3 + h ; h = v -> As
    run_gemm(g_w3t + (size_t)l * HH * HH);
#pragma unroll
    for (int i = 0; i < 8; i++) {
        int lin = i * 256 + tid;
        int r = lin >> 5, c4 = lin & 31;
        int gr = m0 + r;
        float4 v = *(float4*)(Os + r * OP + c4 * 4);
        const float4 bi = *(const float4*)(b3p + c4 * 4);
        v.x += bi.x; v.y += bi.y; v.z += bi.z; v.w += bi.w;
        if (gr < N) {
            float4 o = *(float4*)(h + (size_t)gr * HH + c4 * 4);
            v.x += o.x; v.y += o.y; v.z += o.z; v.w += o.w;
            *(float4*)(h + (size_t)gr * HH + c4 * 4) = v;
        }
        uint2 p;
        __half2 h0 = __floats2half2_rn(v.x, v.y);
        __half2 h1 = __floats2half2_rn(v.z, v.w);
        p.x = *(unsigned int*)&h0;
        p.y = *(unsigned int*)&h1;
        *(uint2*)(As + (size_t)r * AP + c4 * 4) = p;
    }

    // Stage 3: x_next = v @ W1[l+1] -> g_xh
    if (NEXT) {
        run_gemm(g_w1t + (size_t)(l + 1) * HH * HH);
#pragma unroll
        for (int i = 0; i < 8; i++) {
            int lin = i * 256 + tid;
            int r = lin >> 5, c4 = lin & 31;
            int gr = m0 + r;
            if (gr >= N) continue;
            float4 v = *(float4*)(Os + r * OP + c4 * 4);
            uint2 p;
            __half2 h0 = __floats2half2_rn(v.x, v.y);
            __half2 h1 = __floats2half2_rn(v.z, v.w);
            p.x = *(unsigned int*)&h0;
            p.y = *(unsigned int*)&h1;
            *(uint2*)(g_xh + (size_t)gr * HH + c4 * 4) = p;
        }
    }
}

// ---------------- launch ----------------
extern "C" void kernel_launch(void* const* d_in, const int* in_sizes, int n_in,
                              void* d_out, int out_size)
{
    const int*   z      = (const int*)d_in[0];
    const float* pos    = (const float*)d_in[1];
    const int*   ei     = (const int*)d_in[2];
    const float* emb    = (const float*)d_in[3];
    const float* mlp_w1 = (const float*)d_in[4];
    const float* mlp_b1 = (const float*)d_in[5];
    const float* mlp_w2 = (const float*)d_in[6];
    const float* mlp_b2 = (const float*)d_in[7];
    const float* lin1_w = (const float*)d_in[8];
    const float* lin2_w = (const float*)d_in[9];
    const float* lin2_b = (const float*)d_in[10];
    const float* lin_w  = (const float*)d_in[11];
    const float* lin_b  = (const float*)d_in[12];

    const int N = in_sizes[0];
    const int E = in_sizes[2] / 2;
    float* h = (float*)d_out;

    const int SMEM_CHAIN = 64 * AP * 2 + 128 * AP * 2 + 64 * OP * 4;
    static bool s_init = false;
    static cudaStream_t s_csr, s_tab;
    static cudaEvent_t s_evRoot, s_evCsr, s_evTab;
    if (!s_init) {
        cudaFuncSetAttribute(k_chain<true>,
                             cudaFuncAttributeMaxDynamicSharedMemorySize, SMEM_CHAIN);
        cudaFuncSetAttribute(k_chain<false>,
                             cudaFuncAttributeMaxDynamicSharedMemorySize, SMEM_CHAIN);
        cudaStreamCreateWithFlags(&s_csr, cudaStreamNonBlocking);
        cudaStreamCreateWithFlags(&s_tab, cudaStreamNonBlocking);
        cudaEventCreateWithFlags(&s_evRoot, cudaEventDisableTiming);
        cudaEventCreateWithFlags(&s_evCsr, cudaEventDisableTiming);
        cudaEventCreateWithFlags(&s_evTab, cudaEventDisableTiming);
        s_init = true;
    }

    const int gb = (N + 63) / 64;
    const int ga = (N + 7) / 8;

    cudaEventRecord(s_evRoot, 0);
    cudaStreamWaitEvent(s_csr, s_evRoot, 0);
    cudaStreamWaitEvent(s_tab, s_evRoot, 0);

    // CSR stream
    k_zero<<<(N + 255) / 256, 256, 0, s_csr>>>(N);
    k_prep<<<313, 256, 0, s_csr>>>(ei, pos, E);
    k_scan<<<1, 1024, 0, s_csr>>>(N);
    k_scatter<<<313, 256, 0, s_csr>>>(ei, E);
    cudaEventRecord(s_evCsr, s_csr);

    // table stream
    dim3 tg(KTAB / PTS, LL);
    k_table<<<tg, 128, 0, s_tab>>>(mlp_w1, mlp_b1, mlp_w2, mlp_b2);
    cudaEventRecord(s_evTab, s_tab);

    // main stream
    k_wconv<<<(3 * LL * HH * HH + 255) / 256, 256>>>(lin1_w, lin2_w, lin_w);
    k_embed<<<(N * 32 + 255) / 256, 256>>>(z, emb, h, N);
    k_lin1<<<gb, 256>>>(N);

    cudaStreamWaitEvent(0, s_evCsr, 0);
    cudaStreamWaitEvent(0, s_evTab, 0);

    for (int l = 0; l < LL; l++) {
        k_agg<<<ga, 256>>>(l, N);
        if (l < LL - 1)
            k_chain<true><<<gb, 256, SMEM_CHAIN>>>(
                l, lin2_b + (size_t)l * HH, lin_b + (size_t)l * HH, h, N);
        else
            k_chain<false><<<gb, 256, SMEM_CHAIN>>>(
                l, lin2_b + (size_t)l * HH, lin_b + (size_t)l * HH, h, N);
    }
}